// round 9
// baseline (speedup 1.0000x reference)
#include <cuda_runtime.h>
#include <math.h>
#include <stdint.h>

#define NB 8
#define NC 128
#define NH 128
#define NW 128
#define NL (NH*NW)          // 16384
#define NMID 32
#define KTOT 416
#define NPAN 13
#define NFROWS 288          // nsum(128) + diff(128) + silu(32)
#define NGB 512             // gemm blocks (8 b x 64 tiles of 256 pos)
#define NTOT (NB*NC*NL)

// ---------------- device scratch ----------------
__device__ float g_y2[NTOT];
__device__ __align__(16) float g_Fg[(size_t)NB*NFROWS*NL];
__device__ float g_gap[NB][NC];
__device__ __align__(16) float g_Bt[KTOT*NC];
__device__ float g_ck[NB][3][NC];
__device__ float g_u[NB][NMID];
__device__ float g_b2p[NC];
__device__ float g_psum[NC*NGB];
__device__ float g_psq[NC*NGB];
__device__ float g_scale[NC];
__device__ float g_shift[NC];

// ---------------- helpers ----------------
__device__ __forceinline__ float to_tf32(float x) {
    uint32_t o;
    asm("cvt.rna.tf32.f32 %0, %1;" : "=r"(o) : "f"(x));
    return __uint_as_float(o);
}
__device__ __forceinline__ uint32_t cvt_rna_u(uint32_t x) {
    uint32_t o;
    asm("cvt.rna.tf32.f32 %0, %1;" : "=r"(o) : "f"(__uint_as_float(x)));
    return o;
}
__device__ __forceinline__ void mma_tf32(float* d, const uint32_t* a, const uint32_t* b) {
    asm volatile("mma.sync.aligned.m16n8k8.row.col.f32.tf32.tf32.f32 "
        "{%0,%1,%2,%3}, {%4,%5,%6,%7}, {%8,%9}, {%0,%1,%2,%3};"
        : "+f"(d[0]), "+f"(d[1]), "+f"(d[2]), "+f"(d[3])
        : "r"(a[0]), "r"(a[1]), "r"(a[2]), "r"(a[3]), "r"(b[0]), "r"(b[1]));
}
__device__ __forceinline__ uint32_t smem_u32(const void* p) {
    uint32_t a;
    asm("{ .reg .u64 t; cvta.to.shared.u64 t, %1; cvt.u32.u64 %0, t; }" : "=r"(a) : "l"(p));
    return a;
}
__device__ __forceinline__ void cp16(uint32_t d, const void* s, bool pred) {
    int sz = pred ? 16 : 0;
    asm volatile("cp.async.cg.shared.global [%0], [%1], 16, %2;"
                 :: "r"(d), "l"(s), "r"(sz) : "memory");
}
__device__ __forceinline__ void cp_commit() {
    asm volatile("cp.async.commit_group;" ::: "memory");
}
#define CP_WAIT(n) asm volatile("cp.async.wait_group %0;" :: "n"(n) : "memory")

// ---------------- gap ----------------
__global__ void k_gap(const float* __restrict__ x) {
    int bc = blockIdx.x;
    int tid = threadIdx.x;
    __shared__ float red[256];
    const float4* p = (const float4*)(x + (size_t)bc * NL);
    float s = 0.f;
    for (int t = tid; t < NL/4; t += 256) { float4 v = p[t]; s += (v.x + v.y) + (v.z + v.w); }
    red[tid] = s; __syncthreads();
    for (int k = 128; k > 0; k >>= 1) { if (tid < k) red[tid] += red[tid+k]; __syncthreads(); }
    if (tid == 0) g_gap[bc >> 7][bc & 127] = red[0] * (1.0f / NL);
}

// ---------------- fold weights — 512 threads, 4-way K split ----------------
__global__ __launch_bounds__(512) void k_prepw(
        const float* __restrict__ wp,  const float* __restrict__ wout,
        const float* __restrict__ wdw, const float* __restrict__ win,
        const float* __restrict__ w2,  const float* __restrict__ b2,
        const float* __restrict__ dwp) {
    const int o = blockIdx.x, tid = threadIdx.x;
    const int c = tid & 127, part = tid >> 7;
    __shared__ float wps[NC], q[NC];
    __shared__ float par[4][NC], parb[4][NC];
    if (tid < NC) wps[tid] = wp[o*NC + tid];
    __syncthreads();
    {
        float a = 0.f;
        const int t0 = part * 32;
        #pragma unroll 8
        for (int j = 0; j < 32; j++) a = fmaf(wps[t0+j], wout[(t0+j)*NC + c], a);
        par[part][c] = a;
    }
    __syncthreads();
    if (tid < NC) q[tid] = (par[0][tid] + par[1][tid]) + (par[2][tid] + par[3][tid]);
    __syncthreads();
    {
        const int t0 = part * 32;
        float a1 = 0.f, a2 = 0.f;
        #pragma unroll 8
        for (int j = 0; j < 32; j++) {
            int s = t0 + j;
            float qs = q[s];
            float w1v = wdw[s*3 + 1], w02 = wdw[s*3 + 0] + wdw[s*3 + 2];
            float wi = win[s*NC + c];
            a1 = fmaf(qs * w1v, wi, a1);
            a2 = fmaf(qs * w02, wi, a2);
        }
        par[part][c] = a1; parb[part][c] = a2;
    }
    __syncthreads();
    if (tid < NC) {
        float A1 = (par[0][tid] + par[1][tid]) + (par[2][tid] + par[3][tid]) + wps[tid];
        float A2 = 0.25f * ((parb[0][tid] + parb[1][tid]) + (parb[2][tid] + parb[3][tid]));
        g_Bt[tid*NC + o]          = to_tf32(A1);
        g_Bt[(NC + tid)*NC + o]   = to_tf32(A2);
        g_Bt[(2*NC + tid)*NC + o] = to_tf32(dwp[0] * wps[tid]);
    }
    __syncthreads();
    if (tid < NC) {
        int m = tid & 31, p4 = tid >> 5;
        float s4 = 0.f;
        const int t0 = p4 * 32;
        #pragma unroll 8
        for (int j = 0; j < 32; j++) s4 = fmaf(wps[t0+j], w2[(t0+j)*NMID + m], s4);
        par[p4][m] = s4;
        parb[0][tid] = wps[tid] * b2[tid];
    }
    __syncthreads();
    if (tid < 32) {
        g_Bt[(3*NC + tid)*NC + o] =
            to_tf32((par[0][tid] + par[1][tid]) + (par[2][tid] + par[3][tid]));
        float s = (parb[0][tid] + parb[0][tid+32]) + (parb[0][tid+64] + parb[0][tid+96]);
        for (int ofs = 16; ofs; ofs >>= 1) s += __shfl_xor_sync(0xffffffff, s, ofs);
        if (tid == 0) g_b2p[o] = s;
    }
}

// ---------------- per-batch vectors — 1024 threads, 8-way K split ----------------
__global__ __launch_bounds__(1024) void k_prep3(
        const float* __restrict__ wci, const float* __restrict__ wdwch,
        const float* __restrict__ wco, const float* __restrict__ w1) {
    const int b = blockIdx.x, tid = threadIdx.x;
    const int c = tid & 127, part = tid >> 7;
    __shared__ float gs[NC], g2s[NC];
    __shared__ float par[8][NC];
    __shared__ float par3[3][8][NC];
    __shared__ float nrm_s;
    if (tid < NC) { float g = g_gap[b][tid]; par[0][tid] = g * g; }
    __syncthreads();
    if (tid < 32) {
        float s = (par[0][tid] + par[0][tid+32]) + (par[0][tid+64] + par[0][tid+96]);
        for (int o = 16; o; o >>= 1) s += __shfl_xor_sync(0xffffffff, s, o);
        if (tid == 0) nrm_s = fmaxf(sqrtf(s), 1e-12f);
    }
    __syncthreads();
    if (tid < NC) gs[tid] = g_gap[b][tid] / nrm_s;
    __syncthreads();
    {
        float a = 0.f;
        const int t0 = part * 16;
        #pragma unroll
        for (int j = 0; j < 16; j++) a = fmaf(gs[t0+j], wco[(t0+j)*NC + c], a);
        par[part][c] = a;
    }
    __syncthreads();
    if (tid < NC) {
        float a = 0.f;
        #pragma unroll
        for (int p = 0; p < 8; p++) a += par[p][tid];
        g2s[tid] = a;
    }
    __syncthreads();
    {
        const int t0 = part * 16;
        float s0 = 0.f, s1 = 0.f, s2 = 0.f;
        #pragma unroll
        for (int j = 0; j < 16; j++) {
            int t = t0 + j;
            float wv = wci[t*NC + c] * g2s[t];
            s0 = fmaf(wv, wdwch[t*3 + 0], s0);
            s1 = fmaf(wv, wdwch[t*3 + 1], s1);
            s2 = fmaf(wv, wdwch[t*3 + 2], s2);
        }
        par3[0][part][c] = s0; par3[1][part][c] = s1; par3[2][part][c] = s2;
    }
    __syncthreads();
    if (tid < 384) {
        int k = tid >> 7, cc = tid & 127;
        float a = 0.f;
        #pragma unroll
        for (int p = 0; p < 8; p++) a += par3[k][p][cc];
        g_ck[b][k][cc] = a;
    }
    {
        int m = tid & 31, pt = tid >> 5;
        const int t0 = pt * 4;
        float s = 0.f;
        #pragma unroll
        for (int j = 0; j < 4; j++) s = fmaf(w1[m*NC + t0+j], gs[t0+j], s);
        ((float*)par)[pt*32 + m] = s;
    }
    __syncthreads();
    if (tid < NMID) {
        float s = 0.f;
        #pragma unroll
        for (int p = 0; p < 32; p++) s += ((float*)par)[p*32 + tid];
        g_u[b][tid] = s;
    }
}

// ---------------- stencil build — 512 threads ----------------
__global__ __launch_bounds__(512) void k_build(const float* __restrict__ x) {
    const int bx = blockIdx.x;
    const int b = bx >> 7, c = bx & 127;
    const float* xp = x + (size_t)(b*NC + c) * NL;
    float* nrow = g_Fg + (size_t)b*NFROWS*NL + (size_t)c*NL;
    float* drow = nrow + (size_t)NC*NL;
    const int tid = threadIdx.x;
    #pragma unroll 2
    for (int r = 0; r < 8; r++) {
        int p4 = tid + (r << 9);
        int pos = p4 << 2;
        int i = pos >> 7, j0 = pos & 127;
        float4 c4 = ((const float4*)xp)[p4];
        float lprev = (pos > 0) ? xp[pos-1] : 0.f;
        float rnext = (pos < NL-4) ? xp[pos+4] : 0.f;
        float u0,u1,u2,u3, d0,d1,d2,d3;
        if (i > 0) {
            float4 up4 = ((const float4*)xp)[p4-32];
            u0 = up4.x; u1 = up4.y; u2 = up4.z; u3 = up4.w;
        } else {
            u0 = (j0 > 0) ? xp[127*NW + j0-1] : 0.f;
            u1 = xp[127*NW + j0];
            u2 = xp[127*NW + j0+1];
            u3 = xp[127*NW + j0+2];
        }
        if (i < 127) {
            float4 dn4 = ((const float4*)xp)[p4+32];
            d0 = dn4.x; d1 = dn4.y; d2 = dn4.z; d3 = dn4.w;
        } else {
            d0 = xp[j0+1]; d1 = xp[j0+2]; d2 = xp[j0+3];
            d3 = (j0+3 < 127) ? xp[j0+4] : 0.f;
        }
        float l0 = lprev, l1 = c4.x, l2 = c4.y, l3 = c4.z;
        float r0 = c4.y, r1 = c4.z, r2 = c4.w, r3 = rnext;
        ((float4*)nrow)[p4] = make_float4(to_tf32((l0+r0)+(u0+d0)), to_tf32((l1+r1)+(u1+d1)),
                                          to_tf32((l2+r2)+(u2+d2)), to_tf32((l3+r3)+(u3+d3)));
        float lr0 = (j0 == 0) ? c4.y : lprev;
        float rr3 = (j0 == 124) ? c4.z : rnext;
        float ur0,ur1,ur2,ur3, dr0,dr1,dr2,dr3;
        if (i > 0) { ur0=u0; ur1=u1; ur2=u2; ur3=u3; }
        else       { ur0=d0; ur1=d1; ur2=d2; ur3=d3; }
        if (i < 127) { dr0=d0; dr1=d1; dr2=d2; dr3=d3; }
        else         { dr0=u0; dr1=u1; dr2=u2; dr3=u3; }
        float df0 = 0.25f*((fabsf(c4.x-lr0)+fabsf(c4.x-c4.y))+(fabsf(c4.x-ur0)+fabsf(c4.x-dr0)));
        float df1 = 0.25f*((fabsf(c4.y-c4.x)+fabsf(c4.y-c4.z))+(fabsf(c4.y-ur1)+fabsf(c4.y-dr1)));
        float df2 = 0.25f*((fabsf(c4.z-c4.y)+fabsf(c4.z-c4.w))+(fabsf(c4.z-ur2)+fabsf(c4.z-dr2)));
        float df3 = 0.25f*((fabsf(c4.w-c4.z)+fabsf(c4.w-rr3))+(fabsf(c4.w-ur3)+fabsf(c4.w-dr3)));
        ((float4*)drow)[p4] = make_float4(to_tf32(df0), to_tf32(df1), to_tf32(df2), to_tf32(df3));
    }
}

// ---------------- v reduction + silu rows ----------------
__global__ __launch_bounds__(288) void k_vred(const float* __restrict__ x,
                                              const float* __restrict__ b1) {
    __shared__ float s0s[258], s1s[258], s2s[258];
    __shared__ float cks[3*NC], us[NMID], b1s[NMID];
    const int tid = threadIdx.x;
    const int b = blockIdx.x >> 6;
    const int tb = (blockIdx.x & 63) << 8;
    const float* xb = x + (size_t)b * NC * NL;

    for (int q = tid; q < 3*NC; q += 288) cks[q] = (&g_ck[b][0][0])[q];
    if (tid < NMID) { us[tid] = g_u[b][tid]; b1s[tid] = b1[tid]; }
    __syncthreads();

    if (tid < 258) {
        int gpos = tb - 1 + tid;
        float a0 = 0.f, a1 = 0.f, a2 = 0.f;
        if (gpos >= 0 && gpos < NL) {
            const float* px = xb + gpos;
            #pragma unroll 4
            for (int c = 0; c < NC; c++) {
                float xv = px[(size_t)c * NL];
                a0 = fmaf(cks[c], xv, a0);
                a1 = fmaf(cks[NC + c], xv, a1);
                a2 = fmaf(cks[2*NC + c], xv, a2);
            }
        }
        s0s[tid] = a0; s1s[tid] = a1; s2s[tid] = a2;
    }
    __syncthreads();
    if (tid < 256) {
        float v = s0s[tid] + s1s[tid+1] + s2s[tid+2];
        float* dst = g_Fg + (size_t)b*NFROWS*NL + (size_t)(2*NC)*NL + tb + tid;
        #pragma unroll 4
        for (int m = 0; m < NMID; m++) {
            float z = fmaf(us[m], v, b1s[m]);
            dst[(size_t)m * NL] = to_tf32(z / (1.f + __expf(-z)));
        }
    }
}

// ---------------- streaming GEMM: M=128, N=256, 512 threads, 3-stage ring ----------------
// stage = A(32x128, 16KB) + B(32x256, 32KB) = 48KB; 3 stages = 144KB
#define GSMEM (3*12288*4)

__global__ __launch_bounds__(512, 1) void k_gemm(const float* __restrict__ x) {
    extern __shared__ __align__(16) float sm[];
    const int tid = threadIdx.x;
    const int b = blockIdx.x >> 6;
    const int posb = (blockIdx.x & 63) << 8;
    const float* xb  = x + (size_t)b * NC * NL + posb;
    const float* fgb = g_Fg + (size_t)b * NFROWS * NL + posb;

    auto issueP = [&](int p, int st) {
        int k0 = p * 32;
        const float* bsrc = (k0 < NC) ? (xb + (size_t)k0 * NL) : (fgb + (size_t)(k0 - NC) * NL);
        const float* asrc = g_Bt + k0 * NC;
        uint32_t ab = smem_u32(sm + st * 12288);
        uint32_t bb = ab + 16384;
        // A: 1024 float4, 2 per thread
        #pragma unroll
        for (int r = 0; r < 2; r++) {
            int f = tid + (r << 9);
            int kr = f >> 5, j4 = f & 31;
            int sw = (kr*32 + (j4 ^ ((kr & 3) << 1))) * 16;
            cp16(ab + sw, asrc + kr*NC + (j4 << 2), true);
        }
        // B: 2048 float4 (32 rows x 64 f4), 4 per thread
        #pragma unroll
        for (int r = 0; r < 4; r++) {
            int f = tid + (r << 9);
            int kr = f >> 6, j4 = f & 63;
            int sw = (kr*64 + (j4 ^ ((kr & 3) << 1))) * 16;
            cp16(bb + sw, bsrc + (size_t)kr*NL + (j4 << 2), true);
        }
        cp_commit();
    };
    issueP(0, 0); issueP(1, 1);

    const int lane = tid & 31, g = lane >> 2, tg = lane & 3;
    const int w = tid >> 5, mbase = (w >> 3) * 64, nbase = (w & 7) * 32;
    const int swa = tg << 3;
    float dacc[4][4][4];
    #pragma unroll
    for (int mt = 0; mt < 4; mt++)
        #pragma unroll
        for (int nt = 0; nt < 4; nt++)
            #pragma unroll
            for (int qq = 0; qq < 4; qq++) dacc[mt][nt][qq] = 0.f;

    auto mmaPanel = [&](const uint32_t* As, bool cvt) {
        const uint32_t* Fu = As + 4096;
        #pragma unroll
        for (int ks = 0; ks < 4; ks++) {
            const int kr = ks * 8;
            uint32_t af[4][4], bf[4][2];
            #pragma unroll
            for (int nt = 0; nt < 4; nt++) {
                int n = nbase + nt*8 + g;
                uint32_t v0 = Fu[(kr + tg)*256 + (n ^ swa)];
                uint32_t v1 = Fu[(kr + tg + 4)*256 + (n ^ swa)];
                bf[nt][0] = cvt ? cvt_rna_u(v0) : v0;
                bf[nt][1] = cvt ? cvt_rna_u(v1) : v1;
            }
            #pragma unroll
            for (int mt = 0; mt < 4; mt++) {
                int o = mbase + mt*16 + g;
                af[mt][0] = As[(kr + tg)*128 + (o ^ swa)];
                af[mt][1] = As[(kr + tg)*128 + ((o+8) ^ swa)];
                af[mt][2] = As[(kr + tg + 4)*128 + (o ^ swa)];
                af[mt][3] = As[(kr + tg + 4)*128 + ((o+8) ^ swa)];
            }
            #pragma unroll
            for (int mt = 0; mt < 4; mt++)
                #pragma unroll
                for (int nt = 0; nt < 4; nt++)
                    mma_tf32(dacc[mt][nt], af[mt], bf[nt]);
        }
    };

    int st = 0;
    #pragma unroll 1
    for (int p = 0; p < NPAN; p++) {
        if (p < NPAN-1) { CP_WAIT(1); } else { CP_WAIT(0); }
        __syncthreads();
        if (p + 2 < NPAN) issueP(p + 2, (p + 2) % 3);
        mmaPanel((const uint32_t*)(sm + st * 12288), p < 4);
        st = (st == 2) ? 0 : st + 1;
    }
    __syncthreads();

    // ---- epilogue: bias, y2 store, BN partials ----
    float* sred = sm;    // [128][8] sums + [128][8] sumsq
    #pragma unroll
    for (int mt = 0; mt < 4; mt++) {
        int o0 = mbase + mt*16 + g, o1 = o0 + 8;
        float bb0 = g_b2p[o0], bb1 = g_b2p[o1];
        float* row0 = &g_y2[(size_t)(b*NC + o0) * NL + posb];
        float* row1 = &g_y2[(size_t)(b*NC + o1) * NL + posb];
        float s0 = 0.f, q0 = 0.f, s1 = 0.f, q1 = 0.f;
        #pragma unroll
        for (int nt = 0; nt < 4; nt++) {
            float v0 = dacc[mt][nt][0] + bb0, v1 = dacc[mt][nt][1] + bb0;
            float v2 = dacc[mt][nt][2] + bb1, v3 = dacc[mt][nt][3] + bb1;
            int j = nbase + nt*8 + 2*tg;
            *(float2*)(row0 + j) = make_float2(v0, v1);
            *(float2*)(row1 + j) = make_float2(v2, v3);
            s0 += v0 + v1; q0 = fmaf(v0, v0, q0); q0 = fmaf(v1, v1, q0);
            s1 += v2 + v3; q1 = fmaf(v2, v2, q1); q1 = fmaf(v3, v3, q1);
        }
        s0 += __shfl_xor_sync(0xffffffff, s0, 1); s0 += __shfl_xor_sync(0xffffffff, s0, 2);
        q0 += __shfl_xor_sync(0xffffffff, q0, 1); q0 += __shfl_xor_sync(0xffffffff, q0, 2);
        s1 += __shfl_xor_sync(0xffffffff, s1, 1); s1 += __shfl_xor_sync(0xffffffff, s1, 2);
        q1 += __shfl_xor_sync(0xffffffff, q1, 1); q1 += __shfl_xor_sync(0xffffffff, q1, 2);
        if (tg == 0) {
            int nw = w & 7;
            sred[o0*8 + nw] = s0; sred[1024 + o0*8 + nw] = q0;
            sred[o1*8 + nw] = s1; sred[1024 + o1*8 + nw] = q1;
        }
    }
    __syncthreads();
    if (tid < NC) {
        float s = 0.f, q = 0.f;
        #pragma unroll
        for (int t = 0; t < 8; t++) { s += sred[tid*8 + t]; q += sred[1024 + tid*8 + t]; }
        g_psum[tid*NGB + blockIdx.x] = s;
        g_psq [tid*NGB + blockIdx.x] = q;
    }
}

// ---------------- BN stats ----------------
__global__ void k_bnstat(const float* __restrict__ gamma, const float* __restrict__ beta) {
    int c = blockIdx.x, tid = threadIdx.x;
    __shared__ float s1[256], s2[256];
    float a = 0.f, q = 0.f;
    for (int t = tid; t < NGB; t += 256) { a += g_psum[c*NGB + t]; q += g_psq[c*NGB + t]; }
    s1[tid] = a; s2[tid] = q; __syncthreads();
    for (int s = 128; s > 0; s >>= 1) {
        if (tid < s) { s1[tid] += s1[tid+s]; s2[tid] += s2[tid+s]; }
        __syncthreads();
    }
    if (tid == 0) {
        const float invN = 1.0f / (float)(NB * NL);
        float mu  = s1[0] * invN;
        float var = s2[0] * invN - mu * mu;
        float rs  = rsqrtf(var + 1e-5f);
        float sc  = gamma[c] * rs;
        g_scale[c] = sc;
        g_shift[c] = beta[c] - mu * sc;
    }
}

// ---------------- normalize: 512 threads, 2 float4/thread ----------------
__global__ __launch_bounds__(512) void k_norm(float* __restrict__ out) {
    int base = blockIdx.x * 1024 + threadIdx.x;
    #pragma unroll
    for (int r = 0; r < 2; r++) {
        int idx = base + (r << 9);
        float4 v = ((const float4*)g_y2)[idx];
        int c = (idx >> 12) & 127;
        float sc = g_scale[c], sh = g_shift[c];
        v.x = fmaf(v.x, sc, sh); v.y = fmaf(v.y, sc, sh);
        v.z = fmaf(v.z, sc, sh); v.w = fmaf(v.w, sc, sh);
        ((float4*)out)[idx] = v;
    }
}

// ---------------- launcher ----------------
extern "C" void kernel_launch(void* const* d_in, const int* in_sizes, int n_in,
                              void* d_out, int out_size) {
    const float* x            = (const float*)d_in[0];
    const float* w_spatial_in = (const float*)d_in[1];
    const float* w_dw_spatial = (const float*)d_in[2];
    const float* w_spatial_out= (const float*)d_in[3];
    const float* w_ch_in      = (const float*)d_in[4];
    const float* w_ch_dw      = (const float*)d_in[5];
    const float* w_ch_out     = (const float*)d_in[6];
    const float* w_mlp1       = (const float*)d_in[7];
    const float* b_mlp1       = (const float*)d_in[8];
    const float* w_mlp2       = (const float*)d_in[9];
    const float* b_mlp2       = (const float*)d_in[10];
    const float* diff_weight  = (const float*)d_in[11];
    const float* bn_gamma     = (const float*)d_in[12];
    const float* bn_beta      = (const float*)d_in[13];
    const float* w_out_proj   = (const float*)d_in[14];
    float* out = (float*)d_out;

    cudaFuncSetAttribute(k_gemm, cudaFuncAttributeMaxDynamicSharedMemorySize, GSMEM);

    k_prepw<<<NC, 512>>>(w_out_proj, w_spatial_out, w_dw_spatial, w_spatial_in,
                         w_mlp2, b_mlp2, diff_weight);
    k_gap  <<<NB*NC, 256>>>(x);
    k_prep3<<<NB, 1024>>>(w_ch_in, w_ch_dw, w_ch_out, w_mlp1);
    k_build<<<NB*NC, 512>>>(x);
    k_vred <<<NB*64, 288>>>(x, b_mlp1);
    k_gemm <<<NGB, 512, GSMEM>>>(x);
    k_bnstat<<<NC, 256>>>(bn_gamma, bn_beta);
    k_norm <<<NTOT/4/1024, 512>>>(out);
}

// round 11
// speedup vs baseline: 1.1880x; 1.1880x over previous
#include <cuda_runtime.h>
#include <math.h>
#include <stdint.h>

#define NB 8
#define NC 128
#define NH 128
#define NW 128
#define NL (NH*NW)          // 16384
#define NMID 32
#define KTOT 416
#define NPAN 13
#define NFROWS 288          // nsum(128) + diff(128) + silu(32)
#define NROWBLK 1024
#define NTOT (NB*NC*NL)

// ---------------- device scratch ----------------
__device__ __align__(16) float g_Fg[(size_t)NB*NFROWS*NL];
__device__ float g_gap[NB][NC];
__device__ __align__(16) float g_Bt[KTOT*NC];
__device__ float g_ck[NB][3][NC];
__device__ float g_u[NB][NMID];
__device__ float g_b2p[NC];
__device__ float g_psum[NC*NROWBLK];
__device__ float g_psq[NC*NROWBLK];
__device__ float g_scale[NC];
__device__ float g_shift[NC];

// ---------------- helpers ----------------
__device__ __forceinline__ float to_tf32(float x) {
    uint32_t o;
    asm("cvt.rna.tf32.f32 %0, %1;" : "=r"(o) : "f"(x));
    return __uint_as_float(o);
}
__device__ __forceinline__ uint32_t cvt_rna_u(uint32_t x) {
    uint32_t o;
    asm("cvt.rna.tf32.f32 %0, %1;" : "=r"(o) : "f"(__uint_as_float(x)));
    return o;
}
__device__ __forceinline__ void mma_tf32(float* d, const uint32_t* a, const uint32_t* b) {
    asm volatile("mma.sync.aligned.m16n8k8.row.col.f32.tf32.tf32.f32 "
        "{%0,%1,%2,%3}, {%4,%5,%6,%7}, {%8,%9}, {%0,%1,%2,%3};"
        : "+f"(d[0]), "+f"(d[1]), "+f"(d[2]), "+f"(d[3])
        : "r"(a[0]), "r"(a[1]), "r"(a[2]), "r"(a[3]), "r"(b[0]), "r"(b[1]));
}
__device__ __forceinline__ uint32_t smem_u32(const void* p) {
    uint32_t a;
    asm("{ .reg .u64 t; cvta.to.shared.u64 t, %1; cvt.u32.u64 %0, t; }" : "=r"(a) : "l"(p));
    return a;
}
__device__ __forceinline__ void cp16(uint32_t d, const void* s, bool pred) {
    int sz = pred ? 16 : 0;
    asm volatile("cp.async.cg.shared.global [%0], [%1], 16, %2;"
                 :: "r"(d), "l"(s), "r"(sz) : "memory");
}
__device__ __forceinline__ void cp_commit() {
    asm volatile("cp.async.commit_group;" ::: "memory");
}
#define CP_WAIT(n) asm volatile("cp.async.wait_group %0;" :: "n"(n) : "memory")

// ---------------- fold weights — 512 threads, 4-way K split ----------------
__global__ __launch_bounds__(512) void k_prepw(
        const float* __restrict__ wp,  const float* __restrict__ wout,
        const float* __restrict__ wdw, const float* __restrict__ win,
        const float* __restrict__ w2,  const float* __restrict__ b2,
        const float* __restrict__ dwp) {
    const int o = blockIdx.x, tid = threadIdx.x;
    const int c = tid & 127, part = tid >> 7;
    __shared__ float wps[NC], q[NC];
    __shared__ float par[4][NC], parb[4][NC];
    if (tid < NC) wps[tid] = wp[o*NC + tid];
    __syncthreads();
    {
        float a = 0.f;
        const int t0 = part * 32;
        #pragma unroll 8
        for (int j = 0; j < 32; j++) a = fmaf(wps[t0+j], wout[(t0+j)*NC + c], a);
        par[part][c] = a;
    }
    __syncthreads();
    if (tid < NC) q[tid] = (par[0][tid] + par[1][tid]) + (par[2][tid] + par[3][tid]);
    __syncthreads();
    {
        const int t0 = part * 32;
        float a1 = 0.f, a2 = 0.f;
        #pragma unroll 8
        for (int j = 0; j < 32; j++) {
            int s = t0 + j;
            float qs = q[s];
            float w1v = wdw[s*3 + 1], w02 = wdw[s*3 + 0] + wdw[s*3 + 2];
            float wi = win[s*NC + c];
            a1 = fmaf(qs * w1v, wi, a1);
            a2 = fmaf(qs * w02, wi, a2);
        }
        par[part][c] = a1; parb[part][c] = a2;
    }
    __syncthreads();
    if (tid < NC) {
        float A1 = (par[0][tid] + par[1][tid]) + (par[2][tid] + par[3][tid]) + wps[tid];
        float A2 = 0.25f * ((parb[0][tid] + parb[1][tid]) + (parb[2][tid] + parb[3][tid]));
        g_Bt[tid*NC + o]          = to_tf32(A1);
        g_Bt[(NC + tid)*NC + o]   = to_tf32(A2);
        g_Bt[(2*NC + tid)*NC + o] = to_tf32(dwp[0] * wps[tid]);
    }
    __syncthreads();
    if (tid < NC) {
        int m = tid & 31, p4 = tid >> 5;
        float s4 = 0.f;
        const int t0 = p4 * 32;
        #pragma unroll 8
        for (int j = 0; j < 32; j++) s4 = fmaf(wps[t0+j], w2[(t0+j)*NMID + m], s4);
        par[p4][m] = s4;
        parb[0][tid] = wps[tid] * b2[tid];
    }
    __syncthreads();
    if (tid < 32) {
        g_Bt[(3*NC + tid)*NC + o] =
            to_tf32((par[0][tid] + par[1][tid]) + (par[2][tid] + par[3][tid]));
        float s = (parb[0][tid] + parb[0][tid+32]) + (parb[0][tid+64] + parb[0][tid+96]);
        for (int ofs = 16; ofs; ofs >>= 1) s += __shfl_xor_sync(0xffffffff, s, ofs);
        if (tid == 0) g_b2p[o] = s;
    }
}

// ---------------- per-batch vectors — 1024 threads, 8-way K split ----------------
__global__ __launch_bounds__(1024) void k_prep3(
        const float* __restrict__ wci, const float* __restrict__ wdwch,
        const float* __restrict__ wco, const float* __restrict__ w1) {
    const int b = blockIdx.x, tid = threadIdx.x;
    const int c = tid & 127, part = tid >> 7;
    __shared__ float gs[NC], g2s[NC];
    __shared__ float par[8][NC];
    __shared__ float par3[3][8][NC];
    __shared__ float nrm_s;
    if (tid < NC) { float g = g_gap[b][tid]; par[0][tid] = g * g; }
    __syncthreads();
    if (tid < 32) {
        float s = (par[0][tid] + par[0][tid+32]) + (par[0][tid+64] + par[0][tid+96]);
        for (int o = 16; o; o >>= 1) s += __shfl_xor_sync(0xffffffff, s, o);
        if (tid == 0) nrm_s = fmaxf(sqrtf(s), 1e-12f);
    }
    __syncthreads();
    if (tid < NC) gs[tid] = g_gap[b][tid] / nrm_s;
    __syncthreads();
    {
        float a = 0.f;
        const int t0 = part * 16;
        #pragma unroll
        for (int j = 0; j < 16; j++) a = fmaf(gs[t0+j], wco[(t0+j)*NC + c], a);
        par[part][c] = a;
    }
    __syncthreads();
    if (tid < NC) {
        float a = 0.f;
        #pragma unroll
        for (int p = 0; p < 8; p++) a += par[p][tid];
        g2s[tid] = a;
    }
    __syncthreads();
    {
        const int t0 = part * 16;
        float s0 = 0.f, s1 = 0.f, s2 = 0.f;
        #pragma unroll
        for (int j = 0; j < 16; j++) {
            int t = t0 + j;
            float wv = wci[t*NC + c] * g2s[t];
            s0 = fmaf(wv, wdwch[t*3 + 0], s0);
            s1 = fmaf(wv, wdwch[t*3 + 1], s1);
            s2 = fmaf(wv, wdwch[t*3 + 2], s2);
        }
        par3[0][part][c] = s0; par3[1][part][c] = s1; par3[2][part][c] = s2;
    }
    __syncthreads();
    if (tid < 384) {
        int k = tid >> 7, cc = tid & 127;
        float a = 0.f;
        #pragma unroll
        for (int p = 0; p < 8; p++) a += par3[k][p][cc];
        g_ck[b][k][cc] = a;
    }
    {
        int m = tid & 31, pt = tid >> 5;
        const int t0 = pt * 4;
        float s = 0.f;
        #pragma unroll
        for (int j = 0; j < 4; j++) s = fmaf(w1[m*NC + t0+j], gs[t0+j], s);
        ((float*)par)[pt*32 + m] = s;
    }
    __syncthreads();
    if (tid < NMID) {
        float s = 0.f;
        #pragma unroll
        for (int p = 0; p < 32; p++) s += ((float*)par)[p*32 + tid];
        g_u[b][tid] = s;
    }
}

// ---------------- stencil build + fused gap: 512 threads, one (b,c) plane ----------------
__global__ __launch_bounds__(512) void k_build(const float* __restrict__ x) {
    __shared__ float red[512];
    const int bx = blockIdx.x;
    const int b = bx >> 7, c = bx & 127;
    const float* xp = x + (size_t)(b*NC + c) * NL;
    float* nrow = g_Fg + (size_t)b*NFROWS*NL + (size_t)c*NL;
    float* drow = nrow + (size_t)NC*NL;
    const int tid = threadIdx.x;
    float gsum = 0.f;
    #pragma unroll 2
    for (int r = 0; r < 8; r++) {
        int p4 = tid + (r << 9);
        int pos = p4 << 2;
        int i = pos >> 7, j0 = pos & 127;
        float4 c4 = ((const float4*)xp)[p4];
        gsum += (c4.x + c4.y) + (c4.z + c4.w);
        float lprev = (pos > 0) ? xp[pos-1] : 0.f;
        float rnext = (pos < NL-4) ? xp[pos+4] : 0.f;
        float u0,u1,u2,u3, d0,d1,d2,d3;
        if (i > 0) {
            float4 up4 = ((const float4*)xp)[p4-32];
            u0 = up4.x; u1 = up4.y; u2 = up4.z; u3 = up4.w;
        } else {
            u0 = (j0 > 0) ? xp[127*NW + j0-1] : 0.f;
            u1 = xp[127*NW + j0];
            u2 = xp[127*NW + j0+1];
            u3 = xp[127*NW + j0+2];
        }
        if (i < 127) {
            float4 dn4 = ((const float4*)xp)[p4+32];
            d0 = dn4.x; d1 = dn4.y; d2 = dn4.z; d3 = dn4.w;
        } else {
            d0 = xp[j0+1]; d1 = xp[j0+2]; d2 = xp[j0+3];
            d3 = (j0+3 < 127) ? xp[j0+4] : 0.f;
        }
        float l0 = lprev, l1 = c4.x, l2 = c4.y, l3 = c4.z;
        float r0 = c4.y, r1 = c4.z, r2 = c4.w, r3 = rnext;
        ((float4*)nrow)[p4] = make_float4(to_tf32((l0+r0)+(u0+d0)), to_tf32((l1+r1)+(u1+d1)),
                                          to_tf32((l2+r2)+(u2+d2)), to_tf32((l3+r3)+(u3+d3)));
        float lr0 = (j0 == 0) ? c4.y : lprev;
        float rr3 = (j0 == 124) ? c4.z : rnext;
        float ur0,ur1,ur2,ur3, dr0,dr1,dr2,dr3;
        if (i > 0) { ur0=u0; ur1=u1; ur2=u2; ur3=u3; }
        else       { ur0=d0; ur1=d1; ur2=d2; ur3=d3; }
        if (i < 127) { dr0=d0; dr1=d1; dr2=d2; dr3=d3; }
        else         { dr0=u0; dr1=u1; dr2=u2; dr3=u3; }
        float df0 = 0.25f*((fabsf(c4.x-lr0)+fabsf(c4.x-c4.y))+(fabsf(c4.x-ur0)+fabsf(c4.x-dr0)));
        float df1 = 0.25f*((fabsf(c4.y-c4.x)+fabsf(c4.y-c4.z))+(fabsf(c4.y-ur1)+fabsf(c4.y-dr1)));
        float df2 = 0.25f*((fabsf(c4.z-c4.y)+fabsf(c4.z-c4.w))+(fabsf(c4.z-ur2)+fabsf(c4.z-dr2)));
        float df3 = 0.25f*((fabsf(c4.w-c4.z)+fabsf(c4.w-rr3))+(fabsf(c4.w-ur3)+fabsf(c4.w-dr3)));
        ((float4*)drow)[p4] = make_float4(to_tf32(df0), to_tf32(df1), to_tf32(df2), to_tf32(df3));
    }
    red[tid] = gsum;
    __syncthreads();
    for (int k = 256; k > 0; k >>= 1) {
        if (tid < k) red[tid] += red[tid + k];
        __syncthreads();
    }
    if (tid == 0) g_gap[b][c] = red[0] * (1.0f / NL);
}

// ---------------- v reduction + silu rows ----------------
__global__ __launch_bounds__(288) void k_vred(const float* __restrict__ x,
                                              const float* __restrict__ b1) {
    __shared__ float s0s[258], s1s[258], s2s[258];
    __shared__ float cks[3*NC], us[NMID], b1s[NMID];
    const int tid = threadIdx.x;
    const int b = blockIdx.x >> 6;
    const int tb = (blockIdx.x & 63) << 8;
    const float* xb = x + (size_t)b * NC * NL;

    for (int q = tid; q < 3*NC; q += 288) cks[q] = (&g_ck[b][0][0])[q];
    if (tid < NMID) { us[tid] = g_u[b][tid]; b1s[tid] = b1[tid]; }
    __syncthreads();

    if (tid < 258) {
        int gpos = tb - 1 + tid;
        float a0 = 0.f, a1 = 0.f, a2 = 0.f;
        if (gpos >= 0 && gpos < NL) {
            const float* px = xb + gpos;
            #pragma unroll 4
            for (int c = 0; c < NC; c++) {
                float xv = px[(size_t)c * NL];
                a0 = fmaf(cks[c], xv, a0);
                a1 = fmaf(cks[NC + c], xv, a1);
                a2 = fmaf(cks[2*NC + c], xv, a2);
            }
        }
        s0s[tid] = a0; s1s[tid] = a1; s2s[tid] = a2;
    }
    __syncthreads();
    if (tid < 256) {
        float v = s0s[tid] + s1s[tid+1] + s2s[tid+2];
        float* dst = g_Fg + (size_t)b*NFROWS*NL + (size_t)(2*NC)*NL + tb + tid;
        #pragma unroll 4
        for (int m = 0; m < NMID; m++) {
            float z = fmaf(us[m], v, b1s[m]);
            dst[(size_t)m * NL] = to_tf32(z / (1.f + __expf(-z)));
        }
    }
}

// ---------------- streaming GEMM (R8 known-good), writes pre-BN to out ----------------
#define GSMEM (3*8192*4)

__global__ __launch_bounds__(256, 2) void k_gemm(const float* __restrict__ x,
                                                 float* __restrict__ out) {
    extern __shared__ __align__(16) float sm[];
    const int tid = threadIdx.x;
    const int b = blockIdx.x >> 7;
    const int posb = (blockIdx.x & 127) << 7;
    const float* xb  = x + (size_t)b * NC * NL + posb;
    const float* fgb = g_Fg + (size_t)b * NFROWS * NL + posb;

    auto issueP = [&](int p, int st) {
        int k0 = p * 32;
        const float* bsrc = (k0 < NC) ? (xb + (size_t)k0 * NL) : (fgb + (size_t)(k0 - NC) * NL);
        const float* asrc = g_Bt + k0 * NC;
        uint32_t ab = smem_u32(sm + st * 8192);
        uint32_t bb = ab + 16384;
        #pragma unroll
        for (int r = 0; r < 4; r++) {
            int f = tid + (r << 8);
            int kr = f >> 5, j4 = f & 31;
            int sw = (kr*32 + (j4 ^ ((kr & 3) << 1))) * 16;
            cp16(ab + sw, asrc + kr*NC + (j4 << 2), true);
            cp16(bb + sw, bsrc + (size_t)kr*NL + (j4 << 2), true);
        }
        cp_commit();
    };
    issueP(0, 0); issueP(1, 1);

    const int lane = tid & 31, g = lane >> 2, tg = lane & 3;
    const int w = tid >> 5, mbase = (w >> 2) * 64, nbase = (w & 3) * 32;
    const int swa = tg << 3;
    float dacc[4][4][4];
    #pragma unroll
    for (int mt = 0; mt < 4; mt++)
        #pragma unroll
        for (int nt = 0; nt < 4; nt++)
            #pragma unroll
            for (int qq = 0; qq < 4; qq++) dacc[mt][nt][qq] = 0.f;

    auto mmaPanel = [&](const uint32_t* As, bool cvt) {
        const uint32_t* Fu = As + 4096;
        #pragma unroll
        for (int ks = 0; ks < 4; ks++) {
            const int kr = ks * 8;
            uint32_t af[4][4], bf[4][2];
            #pragma unroll
            for (int nt = 0; nt < 4; nt++) {
                int n = nbase + nt*8 + g;
                uint32_t v0 = Fu[(kr + tg)*128 + (n ^ swa)];
                uint32_t v1 = Fu[(kr + tg + 4)*128 + (n ^ swa)];
                bf[nt][0] = cvt ? cvt_rna_u(v0) : v0;
                bf[nt][1] = cvt ? cvt_rna_u(v1) : v1;
            }
            #pragma unroll
            for (int mt = 0; mt < 4; mt++) {
                int o = mbase + mt*16 + g;
                af[mt][0] = As[(kr + tg)*128 + (o ^ swa)];
                af[mt][1] = As[(kr + tg)*128 + ((o+8) ^ swa)];
                af[mt][2] = As[(kr + tg + 4)*128 + (o ^ swa)];
                af[mt][3] = As[(kr + tg + 4)*128 + ((o+8) ^ swa)];
            }
            #pragma unroll
            for (int mt = 0; mt < 4; mt++)
                #pragma unroll
                for (int nt = 0; nt < 4; nt++)
                    mma_tf32(dacc[mt][nt], af[mt], bf[nt]);
        }
    };

    int st = 0;
    #pragma unroll 1
    for (int p = 0; p < NPAN; p++) {
        if (p < NPAN-1) { CP_WAIT(1); } else { CP_WAIT(0); }
        __syncthreads();
        if (p + 2 < NPAN) issueP(p + 2, (p + 2) % 3);
        mmaPanel((const uint32_t*)(sm + st * 8192), p < 4);
        st = (st == 2) ? 0 : st + 1;
    }
    __syncthreads();

    // ---- epilogue: bias, pre-BN store to out, BN partials ----
    float* sred = sm;
    #pragma unroll
    for (int mt = 0; mt < 4; mt++) {
        int o0 = mbase + mt*16 + g, o1 = o0 + 8;
        float bb0 = g_b2p[o0], bb1 = g_b2p[o1];
        float* row0 = &out[(size_t)(b*NC + o0) * NL + posb];
        float* row1 = &out[(size_t)(b*NC + o1) * NL + posb];
        float s0 = 0.f, q0 = 0.f, s1 = 0.f, q1 = 0.f;
        #pragma unroll
        for (int nt = 0; nt < 4; nt++) {
            float v0 = dacc[mt][nt][0] + bb0, v1 = dacc[mt][nt][1] + bb0;
            float v2 = dacc[mt][nt][2] + bb1, v3 = dacc[mt][nt][3] + bb1;
            int j = nbase + nt*8 + 2*tg;
            *(float2*)(row0 + j) = make_float2(v0, v1);
            *(float2*)(row1 + j) = make_float2(v2, v3);
            s0 += v0 + v1; q0 = fmaf(v0, v0, q0); q0 = fmaf(v1, v1, q0);
            s1 += v2 + v3; q1 = fmaf(v2, v2, q1); q1 = fmaf(v3, v3, q1);
        }
        s0 += __shfl_xor_sync(0xffffffff, s0, 1); s0 += __shfl_xor_sync(0xffffffff, s0, 2);
        q0 += __shfl_xor_sync(0xffffffff, q0, 1); q0 += __shfl_xor_sync(0xffffffff, q0, 2);
        s1 += __shfl_xor_sync(0xffffffff, s1, 1); s1 += __shfl_xor_sync(0xffffffff, s1, 2);
        q1 += __shfl_xor_sync(0xffffffff, q1, 1); q1 += __shfl_xor_sync(0xffffffff, q1, 2);
        if (tg == 0) {
            int nwq = w & 3;
            sred[o0*4 + nwq] = s0; sred[512 + o0*4 + nwq] = q0;
            sred[o1*4 + nwq] = s1; sred[512 + o1*4 + nwq] = q1;
        }
    }
    __syncthreads();
    if (tid < NC) {
        float s = 0.f, q = 0.f;
        #pragma unroll
        for (int t = 0; t < 4; t++) { s += sred[tid*4 + t]; q += sred[512 + tid*4 + t]; }
        g_psum[tid*NROWBLK + blockIdx.x] = s;
        g_psq [tid*NROWBLK + blockIdx.x] = q;
    }
}

// ---------------- BN stats ----------------
__global__ void k_bnstat(const float* __restrict__ gamma, const float* __restrict__ beta) {
    int c = blockIdx.x, tid = threadIdx.x;
    __shared__ float s1[256], s2[256];
    float a = 0.f, q = 0.f;
    for (int t = tid; t < NROWBLK; t += 256) { a += g_psum[c*NROWBLK + t]; q += g_psq[c*NROWBLK + t]; }
    s1[tid] = a; s2[tid] = q; __syncthreads();
    for (int s = 128; s > 0; s >>= 1) {
        if (tid < s) { s1[tid] += s1[tid+s]; s2[tid] += s2[tid+s]; }
        __syncthreads();
    }
    if (tid == 0) {
        const float invN = 1.0f / (float)(NB * NL);
        float mu  = s1[0] * invN;
        float var = s2[0] * invN - mu * mu;
        float rs  = rsqrtf(var + 1e-5f);
        float sc  = gamma[c] * rs;
        g_scale[c] = sc;
        g_shift[c] = beta[c] - mu * sc;
    }
}

// ---------------- normalize in place: 512 threads, 2 float4/thread ----------------
__global__ __launch_bounds__(512) void k_norm(float* __restrict__ out) {
    int base = blockIdx.x * 1024 + threadIdx.x;
    #pragma unroll
    for (int r = 0; r < 2; r++) {
        int idx = base + (r << 9);
        float4 v = ((float4*)out)[idx];
        int c = (idx >> 12) & 127;
        float sc = g_scale[c], sh = g_shift[c];
        v.x = fmaf(v.x, sc, sh); v.y = fmaf(v.y, sc, sh);
        v.z = fmaf(v.z, sc, sh); v.w = fmaf(v.w, sc, sh);
        ((float4*)out)[idx] = v;
    }
}

// ---------------- launcher ----------------
extern "C" void kernel_launch(void* const* d_in, const int* in_sizes, int n_in,
                              void* d_out, int out_size) {
    const float* x            = (const float*)d_in[0];
    const float* w_spatial_in = (const float*)d_in[1];
    const float* w_dw_spatial = (const float*)d_in[2];
    const float* w_spatial_out= (const float*)d_in[3];
    const float* w_ch_in      = (const float*)d_in[4];
    const float* w_ch_dw      = (const float*)d_in[5];
    const float* w_ch_out     = (const float*)d_in[6];
    const float* w_mlp1       = (const float*)d_in[7];
    const float* b_mlp1       = (const float*)d_in[8];
    const float* w_mlp2       = (const float*)d_in[9];
    const float* b_mlp2       = (const float*)d_in[10];
    const float* diff_weight  = (const float*)d_in[11];
    const float* bn_gamma     = (const float*)d_in[12];
    const float* bn_beta      = (const float*)d_in[13];
    const float* w_out_proj   = (const float*)d_in[14];
    float* out = (float*)d_out;

    cudaFuncSetAttribute(k_gemm, cudaFuncAttributeMaxDynamicSharedMemorySize, GSMEM);

    k_build<<<NB*NC, 512>>>(x);     // also produces g_gap
    k_prepw<<<NC, 512>>>(w_out_proj, w_spatial_out, w_dw_spatial, w_spatial_in,
                         w_mlp2, b_mlp2, diff_weight);
    k_prep3<<<NB, 1024>>>(w_ch_in, w_ch_dw, w_ch_out, w_mlp1);
    k_vred <<<NB*64, 288>>>(x, b_mlp1);
    k_gemm <<<NROWBLK, 256, GSMEM>>>(x, out);
    k_bnstat<<<NC, 256>>>(bn_gamma, bn_beta);
    k_norm <<<NTOT/4/1024, 512>>>(out);
}